// round 7
// baseline (speedup 1.0000x reference)
#include <cuda_runtime.h>
#include <math.h>
#include <float.h>
#include <stdint.h>

// Problem constants
#define B_  4
#define S_  2048
#define H_  16
#define DK_ 64
#define D_  1024
#define M_  (B_*S_)   // 8192 rows

// Scratch (device globals: no allocation allowed in kernel_launch)
__device__ float g_Q  [(size_t)M_ * D_];
__device__ float g_K  [(size_t)M_ * D_];
__device__ float g_V  [(size_t)M_ * D_];
__device__ float g_AO [(size_t)M_ * D_];   // flash output, pre-rounded to tf32
// tf32-pre-rounded operand copies
__device__ float g_Aq [(size_t)M_ * D_];
__device__ float g_Ak [(size_t)M_ * D_];
__device__ float g_Av [(size_t)M_ * D_];
__device__ float g_Wq [(size_t)D_ * D_];
__device__ float g_Wk [(size_t)D_ * D_];
__device__ float g_Wv [(size_t)D_ * D_];
__device__ float g_Wo [(size_t)D_ * D_];

// ----------------------------------------------------------------------------
// helpers
// ----------------------------------------------------------------------------
__device__ __forceinline__ uint32_t s2u(const void* p) {
    return (uint32_t)__cvta_generic_to_shared(p);
}
__device__ __forceinline__ void cp_async16(uint32_t dst, const void* src) {
    asm volatile("cp.async.cg.shared.global [%0], [%1], 16;" :: "r"(dst), "l"(src));
}
__device__ __forceinline__ uint32_t f2tf(float x) {
    uint32_t r;
    asm("cvt.rna.tf32.f32 %0, %1;" : "=r"(r) : "f"(x));
    return r;
}
__device__ __forceinline__ void mma_tf32(float c[4],
                                         uint32_t a0, uint32_t a1, uint32_t a2, uint32_t a3,
                                         uint32_t b0, uint32_t b1) {
    asm volatile(
        "mma.sync.aligned.m16n8k8.row.col.f32.tf32.tf32.f32 "
        "{%0,%1,%2,%3}, {%4,%5,%6,%7}, {%8,%9}, {%0,%1,%2,%3};"
        : "+f"(c[0]), "+f"(c[1]), "+f"(c[2]), "+f"(c[3])
        : "r"(a0), "r"(a1), "r"(a2), "r"(a3), "r"(b0), "r"(b1));
}

// Fast exp on FMA/ALU pipes only (no MUFU). Input clamped to [-87, 0];
// magic-number round + degree-5 2^f poly + exponent-bit scale.
__device__ __forceinline__ float fexp(float x) {
    x = fmaxf(x, -87.0f);
    const float MAGIC = 12582912.0f;           // 1.5 * 2^23
    float y  = x * 1.44269504089f;
    float t  = y + MAGIC;
    int   e  = __float_as_int(t) - 0x4B400000;
    float nf = t - MAGIC;
    float f  = y - nf;
    float p  = 1.33335581e-3f;
    p = fmaf(p, f, 9.61812910e-3f);
    p = fmaf(p, f, 5.55041087e-2f);
    p = fmaf(p, f, 2.40226507e-1f);
    p = fmaf(p, f, 6.93147180e-1f);
    p = fmaf(p, f, 1.0f);
    float sc = __int_as_float((e + 127) << 23);
    return p * sc;
}

// ----------------------------------------------------------------------------
// Elementwise tf32 pre-rounding: out[i] = rna_tf32(in[i]) as f32 bit pattern.
// After this, mma.tf32 hardware truncation is the identity -> GEMM needs
// NO per-fragment cvt (bit-identical numerics to cvt-at-use).
// ----------------------------------------------------------------------------
__global__ __launch_bounds__(256)
void round_tf32_kernel(const float* __restrict__ in, float* __restrict__ out, int n4)
{
    int i = blockIdx.x * blockDim.x + threadIdx.x;
    int stride = gridDim.x * blockDim.x;
    for (; i < n4; i += stride) {
        float4 v = *(const float4*)&in[(size_t)i * 4];
        float4 r;
        r.x = __uint_as_float(f2tf(v.x));
        r.y = __uint_as_float(f2tf(v.y));
        r.z = __uint_as_float(f2tf(v.z));
        r.w = __uint_as_float(f2tf(v.w));
        *(float4*)&out[(size_t)i * 4] = r;
    }
}

// ----------------------------------------------------------------------------
// TF32 tensor-core GEMM + bias. Operands MUST be pre-rounded to tf32.
// 128x128 CTA tile, 8 warps (4x2), warp tile 32x64, mma m16n8k8.
// K chunks of 32, cp.async double-buffered. NO cvt in the hot loop:
// raw f32 bits feed mma directly.
// ----------------------------------------------------------------------------
#define APITCH 36
#define BPITCH 132
#define KC     32
#define ABUF   (128 * APITCH)
#define BBUF   (KC * BPITCH)

extern __shared__ float gm_sm[];

__global__ __launch_bounds__(256, 2)
void tf32_gemm_bias_kernel(const float* __restrict__ A, const float* __restrict__ W,
                           const float* __restrict__ bias, float* __restrict__ C,
                           int M, int N, int K)
{
    float* As[2] = { gm_sm,            gm_sm + ABUF };
    float* Bs[2] = { gm_sm + 2*ABUF,   gm_sm + 2*ABUF + BBUF };

    const int tid  = threadIdx.x;
    const int wid  = tid >> 5;
    const int lane = tid & 31;
    const int lr   = lane >> 2;
    const int lc   = lane & 3;
    const int wm   = (wid & 3) * 32;
    const int wn   = (wid >> 2) * 64;
    const int m0   = blockIdx.y * 128;
    const int n0   = blockIdx.x * 128;

    float c[2][8][4];
#pragma unroll
    for (int mt = 0; mt < 2; mt++)
#pragma unroll
        for (int nt = 0; nt < 8; nt++)
#pragma unroll
            for (int j = 0; j < 4; j++) c[mt][nt][j] = 0.f;

    const int NC = K / KC;

    auto load_chunk = [&](int k0, int buf) {
#pragma unroll
        for (int i = 0; i < 4; i++) {
            int idx  = tid + i * 256;
            int row  = idx >> 3;
            int kc   = (idx & 7) * 4;
            cp_async16(s2u(&As[buf][row * APITCH + kc]),
                       A + (size_t)(m0 + row) * K + k0 + kc);
        }
#pragma unroll
        for (int i = 0; i < 4; i++) {
            int idx  = tid + i * 256;
            int krow = idx >> 5;
            int nc   = (idx & 31) * 4;
            cp_async16(s2u(&Bs[buf][krow * BPITCH + nc]),
                       W + (size_t)(k0 + krow) * N + n0 + nc);
        }
    };

    load_chunk(0, 0);
    asm volatile("cp.async.commit_group;");

    for (int ch = 0; ch < NC; ch++) {
        if (ch + 1 < NC) {
            load_chunk((ch + 1) * KC, (ch + 1) & 1);
            asm volatile("cp.async.commit_group;");
            asm volatile("cp.async.wait_group 1;");
        } else {
            asm volatile("cp.async.wait_group 0;");
        }
        __syncthreads();

        const float* Ab = As[ch & 1];
        const float* Bb = Bs[ch & 1];

#pragma unroll
        for (int ks = 0; ks < 4; ks++) {
            const int kb = ks * 8;
            uint32_t af[2][4];
#pragma unroll
            for (int mt = 0; mt < 2; mt++) {
                const float* ap = &Ab[(wm + mt * 16 + lr) * APITCH + kb + lc];
                af[mt][0] = __float_as_uint(ap[0]);
                af[mt][1] = __float_as_uint(ap[8 * APITCH]);
                af[mt][2] = __float_as_uint(ap[4]);
                af[mt][3] = __float_as_uint(ap[8 * APITCH + 4]);
            }
            uint32_t bf[8][2];
#pragma unroll
            for (int nt = 0; nt < 8; nt++) {
                const float* bp = &Bb[(kb + lc) * BPITCH + wn + nt * 8 + lr];
                bf[nt][0] = __float_as_uint(bp[0]);
                bf[nt][1] = __float_as_uint(bp[4 * BPITCH]);
            }
#pragma unroll
            for (int mt = 0; mt < 2; mt++)
#pragma unroll
                for (int nt = 0; nt < 8; nt++)
                    mma_tf32(c[mt][nt], af[mt][0], af[mt][1], af[mt][2], af[mt][3],
                             bf[nt][0], bf[nt][1]);
        }
        __syncthreads();
    }

#pragma unroll
    for (int nt = 0; nt < 8; nt++) {
        const int col = n0 + wn + nt * 8 + lc * 2;
        const float2 bj = *(const float2*)&bias[col];
#pragma unroll
        for (int mt = 0; mt < 2; mt++) {
            const int row0 = m0 + wm + mt * 16 + lr;
            float2 v0, v1;
            v0.x = c[mt][nt][0] + bj.x;  v0.y = c[mt][nt][1] + bj.y;
            v1.x = c[mt][nt][2] + bj.x;  v1.y = c[mt][nt][3] + bj.y;
            *(float2*)&C[(size_t)row0 * N + col]       = v0;
            *(float2*)&C[(size_t)(row0 + 8) * N + col] = v1;
        }
    }
}

// ----------------------------------------------------------------------------
// Flash attention v3 (fp32, online softmax), 4 q-rows x 8 cols per thread.
// CTA = (b, h, 128 q-rows), KV tiles of 64, 256 threads.
// Conflict-free Kt transpose, XOR-swizzled rows, FMA-pipe exp.
// Output is tf32-pre-rounded for the downstream O-projection GEMM.
// ----------------------------------------------------------------------------
#define QT    128
#define KT    64
#define PITCH 68

__device__ __forceinline__ int swz(int c) { return c ^ ((c & 32) >> 3); }

extern __shared__ float fa_sm[];

__global__ __launch_bounds__(256, 2)
void flash_attn_kernel(const float* __restrict__ Q, const float* __restrict__ K,
                       const float* __restrict__ V, float* __restrict__ O)
{
    float* Qs = fa_sm;                    // [128][PITCH] Q natural
    float* Kt = Qs + 128 * PITCH;         // [64][PITCH]  Kt[dk][key_swz]
    float* Vs = Kt + 64 * PITCH;          // [64][PITCH]  Vs[key][dk_swz]
    float* Ps = Vs + 64 * PITCH;          // [128][PITCH] probs

    const int tid  = threadIdx.x;
    const int q0   = blockIdx.x * QT;
    const int h    = blockIdx.y;
    const int b    = blockIdx.z;
    const int hoff = h * DK_;
    const int ty   = tid >> 3;   // 0..31
    const int tx   = tid & 7;    // 0..7
    const int c0   = swz(tx * 8);
    const int c1   = swz(tx * 8 + 4);

    // Load Q tile (128x64), natural layout
#pragma unroll
    for (int i = 0; i < 8; i++) {
        int idx = tid + i * 256;
        int row = idx >> 4;
        int cg  = (idx & 15) * 4;
        float4 v = *(const float4*)&Q[(size_t)(b * S_ + q0 + row) * D_ + hoff + cg];
        *(float4*)&Qs[row * PITCH + cg] = v;
    }

    float mr[4], lr_[4];
    float o[4][8];
#pragma unroll
    for (int r = 0; r < 4; r++) {
        mr[r] = -1e30f;  lr_[r] = 0.f;
#pragma unroll
        for (int j = 0; j < 8; j++) o[r][j] = 0.f;
    }

    for (int kt = 0; kt < S_; kt += KT) {
        __syncthreads();  // prior-iter Ps/Vs reads done (and Qs stores on iter 0)

        // K: conflict-free transpose store. lane map: key = u&63, cg = ((u>>6)&15)*4
#pragma unroll
        for (int i = 0; i < 4; i++) {
            int u   = tid + i * 256;
            int key = u & 63;
            int cg  = ((u >> 6) & 15) * 4;
            float4 kv = *(const float4*)&K[(size_t)(b * S_ + kt + key) * D_ + hoff + cg];
            int kp  = swz(key);
            Kt[(cg + 0) * PITCH + kp] = kv.x;
            Kt[(cg + 1) * PITCH + kp] = kv.y;
            Kt[(cg + 2) * PITCH + kp] = kv.z;
            Kt[(cg + 3) * PITCH + kp] = kv.w;
        }
        // V: natural store, dk swizzled
#pragma unroll
        for (int i = 0; i < 4; i++) {
            int u   = tid + i * 256;
            int row = u >> 4;            // 0..63
            int cg  = (u & 15) * 4;
            float4 vv = *(const float4*)&V[(size_t)(b * S_ + kt + row) * D_ + hoff + cg];
            *(float4*)&Vs[row * PITCH + swz(cg)] = vv;
        }
        __syncthreads();

        // S[r][j] = Q[row_r,:] . K[tx*8+j,:]
        float s[4][8];
#pragma unroll
        for (int r = 0; r < 4; r++)
#pragma unroll
            for (int j = 0; j < 8; j++) s[r][j] = 0.f;

        const float* qp0 = &Qs[ty * PITCH];
        const float* qp1 = &Qs[(ty + 32) * PITCH];
        const float* qp2 = &Qs[(ty + 64) * PITCH];
        const float* qp3 = &Qs[(ty + 96) * PITCH];
        for (int kk = 0; kk < 64; kk++) {
            float qa = qp0[kk];
            float qb = qp1[kk];
            float qc = qp2[kk];
            float qd = qp3[kk];
            const float* kr = &Kt[kk * PITCH];
            float4 k0 = *(const float4*)&kr[c0];
            float4 k1 = *(const float4*)&kr[c1];
            s[0][0] = fmaf(qa, k0.x, s[0][0]); s[0][1] = fmaf(qa, k0.y, s[0][1]);
            s[0][2] = fmaf(qa, k0.z, s[0][2]); s[0][3] = fmaf(qa, k0.w, s[0][3]);
            s[0][4] = fmaf(qa, k1.x, s[0][4]); s[0][5] = fmaf(qa, k1.y, s[0][5]);
            s[0][6] = fmaf(qa, k1.z, s[0][6]); s[0][7] = fmaf(qa, k1.w, s[0][7]);
            s[1][0] = fmaf(qb, k0.x, s[1][0]); s[1][1] = fmaf(qb, k0.y, s[1][1]);
            s[1][2] = fmaf(qb, k0.z, s[1][2]); s[1][3] = fmaf(qb, k0.w, s[1][3]);
            s[1][4] = fmaf(qb, k1.x, s[1][4]); s[1][5] = fmaf(qb, k1.y, s[1][5]);
            s[1][6] = fmaf(qb, k1.z, s[1][6]); s[1][7] = fmaf(qb, k1.w, s[1][7]);
            s[2][0] = fmaf(qc, k0.x, s[2][0]); s[2][1] = fmaf(qc, k0.y, s[2][1]);
            s[2][2] = fmaf(qc, k0.z, s[2][2]); s[2][3] = fmaf(qc, k0.w, s[2][3]);
            s[2][4] = fmaf(qc, k1.x, s[2][4]); s[2][5] = fmaf(qc, k1.y, s[2][5]);
            s[2][6] = fmaf(qc, k1.z, s[2][6]); s[2][7] = fmaf(qc, k1.w, s[2][7]);
            s[3][0] = fmaf(qd, k0.x, s[3][0]); s[3][1] = fmaf(qd, k0.y, s[3][1]);
            s[3][2] = fmaf(qd, k0.z, s[3][2]); s[3][3] = fmaf(qd, k0.w, s[3][3]);
            s[3][4] = fmaf(qd, k1.x, s[3][4]); s[3][5] = fmaf(qd, k1.y, s[3][5]);
            s[3][6] = fmaf(qd, k1.z, s[3][6]); s[3][7] = fmaf(qd, k1.w, s[3][7]);
        }

        // per-row softmax update (reduce across 8-thread tx octet)
#pragma unroll
        for (int r = 0; r < 4; r++) {
            float tmax = -1e30f;
#pragma unroll
            for (int j = 0; j < 8; j++) {
                s[r][j] *= 0.125f;   // 1/sqrt(64)
                tmax = fmaxf(tmax, s[r][j]);
            }
            tmax = fmaxf(tmax, __shfl_xor_sync(0xffffffffu, tmax, 1));
            tmax = fmaxf(tmax, __shfl_xor_sync(0xffffffffu, tmax, 2));
            tmax = fmaxf(tmax, __shfl_xor_sync(0xffffffffu, tmax, 4));

            float mn    = fmaxf(mr[r], tmax);
            float alpha = fexp(mr[r] - mn);
            float psum  = 0.f;
#pragma unroll
            for (int j = 0; j < 8; j++) {
                float p = fexp(s[r][j] - mn);
                s[r][j] = p;
                psum += p;
            }
            psum += __shfl_xor_sync(0xffffffffu, psum, 1);
            psum += __shfl_xor_sync(0xffffffffu, psum, 2);
            psum += __shfl_xor_sync(0xffffffffu, psum, 4);
            lr_[r] = lr_[r] * alpha + psum;
            mr[r]  = mn;
#pragma unroll
            for (int j = 0; j < 8; j++) o[r][j] *= alpha;
        }

        // publish probs
#pragma unroll
        for (int r = 0; r < 4; r++) {
            float* pr = &Ps[(ty + 32 * r) * PITCH + tx * 8];
            *(float4*)&pr[0] = make_float4(s[r][0], s[r][1], s[r][2], s[r][3]);
            *(float4*)&pr[4] = make_float4(s[r][4], s[r][5], s[r][6], s[r][7]);
        }
        __syncthreads();

        // O[row_r, c] += sum_k P[row_r,k] * V[k,c]
        const float* pp0 = &Ps[ty * PITCH];
        const float* pp1 = &Ps[(ty + 32) * PITCH];
        const float* pp2 = &Ps[(ty + 64) * PITCH];
        const float* pp3 = &Ps[(ty + 96) * PITCH];
        for (int k = 0; k < 64; k++) {
            float p0 = pp0[k];
            float p1 = pp1[k];
            float p2 = pp2[k];
            float p3 = pp3[k];
            const float* vr = &Vs[k * PITCH];
            float4 v0 = *(const float4*)&vr[c0];
            float4 v1 = *(const float4*)&vr[c1];
            o[0][0] = fmaf(p0, v0.x, o[0][0]); o[0][1] = fmaf(p0, v0.y, o[0][1]);
            o[0][2] = fmaf(p0, v0.z, o[0][2]); o[0][3] = fmaf(p0, v0.w, o[0][3]);
            o[0][4] = fmaf(p0, v1.x, o[0][4]); o[0][5] = fmaf(p0, v1.y, o[0][5]);
            o[0][6] = fmaf(p0, v1.z, o[0][6]); o[0][7] = fmaf(p0, v1.w, o[0][7]);
            o[1][0] = fmaf(p1, v0.x, o[1][0]); o[1][1] = fmaf(p1, v0.y, o[1][1]);
            o[1][2] = fmaf(p1, v0.z, o[1][2]); o[1][3] = fmaf(p1, v0.w, o[1][3]);
            o[1][4] = fmaf(p1, v1.x, o[1][4]); o[1][5] = fmaf(p1, v1.y, o[1][5]);
            o[1][6] = fmaf(p1, v1.z, o[1][6]); o[1][7] = fmaf(p1, v1.w, o[1][7]);
            o[2][0] = fmaf(p2, v0.x, o[2][0]); o[2][1] = fmaf(p2, v0.y, o[2][1]);
            o[2][2] = fmaf(p2, v0.z, o[2][2]); o[2][3] = fmaf(p2, v0.w, o[2][3]);
            o[2][4] = fmaf(p2, v1.x, o[2][4]); o[2][5] = fmaf(p2, v1.y, o[2][5]);
            o[2][6] = fmaf(p2, v1.z, o[2][6]); o[2][7] = fmaf(p2, v1.w, o[2][7]);
            o[3][0] = fmaf(p3, v0.x, o[3][0]); o[3][1] = fmaf(p3, v0.y, o[3][1]);
            o[3][2] = fmaf(p3, v0.z, o[3][2]); o[3][3] = fmaf(p3, v0.w, o[3][3]);
            o[3][4] = fmaf(p3, v1.x, o[3][4]); o[3][5] = fmaf(p3, v1.y, o[3][5]);
            o[3][6] = fmaf(p3, v1.z, o[3][6]); o[3][7] = fmaf(p3, v1.w, o[3][7]);
        }
    }

    // normalize + tf32-round + write (O feeds the tf32 O-projection GEMM)
#pragma unroll
    for (int r = 0; r < 4; r++) {
        float inv = 1.f / lr_[r];
        float* op = &O[(size_t)(b * S_ + q0 + ty + 32 * r) * D_ + hoff + tx * 8];
        float4 w0, w1;
        w0.x = __uint_as_float(f2tf(o[r][0] * inv));
        w0.y = __uint_as_float(f2tf(o[r][1] * inv));
        w0.z = __uint_as_float(f2tf(o[r][2] * inv));
        w0.w = __uint_as_float(f2tf(o[r][3] * inv));
        w1.x = __uint_as_float(f2tf(o[r][4] * inv));
        w1.y = __uint_as_float(f2tf(o[r][5] * inv));
        w1.z = __uint_as_float(f2tf(o[r][6] * inv));
        w1.w = __uint_as_float(f2tf(o[r][7] * inv));
        *(float4*)&op[0] = w0;
        *(float4*)&op[4] = w1;
    }
}

// ----------------------------------------------------------------------------
// Launch: pre-round operands -> 3 projection GEMMs -> flash -> output GEMM
// ----------------------------------------------------------------------------
extern "C" void kernel_launch(void* const* d_in, const int* in_sizes, int n_in,
                              void* d_out, int out_size)
{
    const float* query = (const float*)d_in[0];
    const float* value = (const float*)d_in[1];
    const float* key   = (const float*)d_in[2];
    const float* Wq = (const float*)d_in[3];
    const float* bq = (const float*)d_in[4];
    const float* Wk = (const float*)d_in[5];
    const float* bk = (const float*)d_in[6];
    const float* Wv = (const float*)d_in[7];
    const float* bv = (const float*)d_in[8];
    const float* Wo = (const float*)d_in[9];
    const float* bo = (const float*)d_in[10];
    float* out = (float*)d_out;

    float *Qp, *Kp, *Vp, *AOp;
    float *Aq, *Ak, *Av, *Wqp, *Wkp, *Wvp, *Wop;
    cudaGetSymbolAddress((void**)&Qp,  g_Q);
    cudaGetSymbolAddress((void**)&Kp,  g_K);
    cudaGetSymbolAddress((void**)&Vp,  g_V);
    cudaGetSymbolAddress((void**)&AOp, g_AO);
    cudaGetSymbolAddress((void**)&Aq,  g_Aq);
    cudaGetSymbolAddress((void**)&Ak,  g_Ak);
    cudaGetSymbolAddress((void**)&Av,  g_Av);
    cudaGetSymbolAddress((void**)&Wqp, g_Wq);
    cudaGetSymbolAddress((void**)&Wkp, g_Wk);
    cudaGetSymbolAddress((void**)&Wvp, g_Wv);
    cudaGetSymbolAddress((void**)&Wop, g_Wo);

    // Pre-round all GEMM operands to tf32 (bit-exact vs cvt-at-use)
    const int n4_act = (M_ * D_) / 4;   // 2,097,152
    const int n4_w   = (D_ * D_) / 4;   //   262,144
    round_tf32_kernel<<<592, 256>>>(query, Aq,  n4_act);
    round_tf32_kernel<<<592, 256>>>(key,   Ak,  n4_act);
    round_tf32_kernel<<<592, 256>>>(value, Av,  n4_act);
    round_tf32_kernel<<<296, 256>>>(Wq,    Wqp, n4_w);
    round_tf32_kernel<<<296, 256>>>(Wk,    Wkp, n4_w);
    round_tf32_kernel<<<296, 256>>>(Wv,    Wvp, n4_w);
    round_tf32_kernel<<<296, 256>>>(Wo,    Wop, n4_w);

    const int gemm_smem = 2 * (ABUF + BBUF) * (int)sizeof(float);  // 70656 B
    cudaFuncSetAttribute(tf32_gemm_bias_kernel,
                         cudaFuncAttributeMaxDynamicSharedMemorySize, gemm_smem);

    dim3 gemm_grid(D_ / 128, M_ / 128);
    tf32_gemm_bias_kernel<<<gemm_grid, 256, gemm_smem>>>(Aq, Wqp, bq, Qp, M_, D_, D_);
    tf32_gemm_bias_kernel<<<gemm_grid, 256, gemm_smem>>>(Ak, Wkp, bk, Kp, M_, D_, D_);
    tf32_gemm_bias_kernel<<<gemm_grid, 256, gemm_smem>>>(Av, Wvp, bv, Vp, M_, D_, D_);

    const int fa_smem = (128 + 64 + 64 + 128) * PITCH * (int)sizeof(float); // 104448
    cudaFuncSetAttribute(flash_attn_kernel,
                         cudaFuncAttributeMaxDynamicSharedMemorySize, fa_smem);
    flash_attn_kernel<<<dim3(S_ / QT, H_, B_), 256, fa_smem>>>(Qp, Kp, Vp, AOp);

    tf32_gemm_bias_kernel<<<gemm_grid, 256, gemm_smem>>>(AOp, Wop, bo, out, M_, D_, D_);
}

// round 8
// speedup vs baseline: 1.8711x; 1.8711x over previous
#include <cuda_runtime.h>
#include <math.h>
#include <float.h>
#include <stdint.h>

// Problem constants
#define B_  4
#define S_  2048
#define H_  16
#define DK_ 64
#define D_  1024
#define M_  (B_*S_)   // 8192 rows

// Scratch (device globals: no allocation allowed in kernel_launch)
__device__ float g_Q [(size_t)M_ * D_];
__device__ float g_K [(size_t)M_ * D_];
__device__ float g_V [(size_t)M_ * D_];
__device__ float g_AO[(size_t)M_ * D_];

// ----------------------------------------------------------------------------
// helpers
// ----------------------------------------------------------------------------
__device__ __forceinline__ uint32_t s2u(const void* p) {
    return (uint32_t)__cvta_generic_to_shared(p);
}
__device__ __forceinline__ void cp_async16(uint32_t dst, const void* src) {
    asm volatile("cp.async.cg.shared.global [%0], [%1], 16;" :: "r"(dst), "l"(src));
}
__device__ __forceinline__ uint32_t f2tf(float x) {
    uint32_t r;
    asm("cvt.rna.tf32.f32 %0, %1;" : "=r"(r) : "f"(x));
    return r;
}
__device__ __forceinline__ float f2tff(float x) {   // rounded value as float
    return __uint_as_float(f2tf(x));
}
__device__ __forceinline__ void mma_tf32(float c[4],
                                         uint32_t a0, uint32_t a1, uint32_t a2, uint32_t a3,
                                         uint32_t b0, uint32_t b1) {
    asm volatile(
        "mma.sync.aligned.m16n8k8.row.col.f32.tf32.tf32.f32 "
        "{%0,%1,%2,%3}, {%4,%5,%6,%7}, {%8,%9}, {%0,%1,%2,%3};"
        : "+f"(c[0]), "+f"(c[1]), "+f"(c[2]), "+f"(c[3])
        : "r"(a0), "r"(a1), "r"(a2), "r"(a3), "r"(b0), "r"(b1));
}

// Fast exp on FMA/ALU pipes only (no MUFU). Input clamped to [-87, 0].
__device__ __forceinline__ float fexp(float x) {
    x = fmaxf(x, -87.0f);
    const float MAGIC = 12582912.0f;           // 1.5 * 2^23
    float y  = x * 1.44269504089f;
    float t  = y + MAGIC;
    int   e  = __float_as_int(t) - 0x4B400000;
    float nf = t - MAGIC;
    float f  = y - nf;
    float p  = 1.33335581e-3f;
    p = fmaf(p, f, 9.61812910e-3f);
    p = fmaf(p, f, 5.55041087e-2f);
    p = fmaf(p, f, 2.40226507e-1f);
    p = fmaf(p, f, 6.93147180e-1f);
    p = fmaf(p, f, 1.0f);
    float sc = __int_as_float((e + 127) << 23);
    return p * sc;
}

// ----------------------------------------------------------------------------
// TF32 tensor-core GEMM + bias (round-6 version — measured ~115us each)
// ----------------------------------------------------------------------------
#define APITCH 36
#define BPITCH 132
#define KC     32
#define ABUF   (128 * APITCH)
#define BBUF   (KC * BPITCH)

extern __shared__ float gm_sm[];

__global__ __launch_bounds__(256, 2)
void tf32_gemm_bias_kernel(const float* __restrict__ A, const float* __restrict__ W,
                           const float* __restrict__ bias, float* __restrict__ C,
                           int M, int N, int K)
{
    float* As[2] = { gm_sm,            gm_sm + ABUF };
    float* Bs[2] = { gm_sm + 2*ABUF,   gm_sm + 2*ABUF + BBUF };

    const int tid  = threadIdx.x;
    const int wid  = tid >> 5;
    const int lane = tid & 31;
    const int lr   = lane >> 2;
    const int lc   = lane & 3;
    const int wm   = (wid & 3) * 32;
    const int wn   = (wid >> 2) * 64;
    const int m0   = blockIdx.y * 128;
    const int n0   = blockIdx.x * 128;

    float c[2][8][4];
#pragma unroll
    for (int mt = 0; mt < 2; mt++)
#pragma unroll
        for (int nt = 0; nt < 8; nt++)
#pragma unroll
            for (int j = 0; j < 4; j++) c[mt][nt][j] = 0.f;

    const int NC = K / KC;

    auto load_chunk = [&](int k0, int buf) {
#pragma unroll
        for (int i = 0; i < 4; i++) {
            int idx  = tid + i * 256;
            int row  = idx >> 3;
            int kc   = (idx & 7) * 4;
            cp_async16(s2u(&As[buf][row * APITCH + kc]),
                       A + (size_t)(m0 + row) * K + k0 + kc);
        }
#pragma unroll
        for (int i = 0; i < 4; i++) {
            int idx  = tid + i * 256;
            int krow = idx >> 5;
            int nc   = (idx & 31) * 4;
            cp_async16(s2u(&Bs[buf][krow * BPITCH + nc]),
                       W + (size_t)(k0 + krow) * N + n0 + nc);
        }
    };

    load_chunk(0, 0);
    asm volatile("cp.async.commit_group;");

    for (int ch = 0; ch < NC; ch++) {
        if (ch + 1 < NC) {
            load_chunk((ch + 1) * KC, (ch + 1) & 1);
            asm volatile("cp.async.commit_group;");
            asm volatile("cp.async.wait_group 1;");
        } else {
            asm volatile("cp.async.wait_group 0;");
        }
        __syncthreads();

        const float* Ab = As[ch & 1];
        const float* Bb = Bs[ch & 1];

#pragma unroll
        for (int ks = 0; ks < 4; ks++) {
            const int kb = ks * 8;
            uint32_t af[2][4];
#pragma unroll
            for (int mt = 0; mt < 2; mt++) {
                const float* ap = &Ab[(wm + mt * 16 + lr) * APITCH + kb + lc];
                af[mt][0] = f2tf(ap[0]);
                af[mt][1] = f2tf(ap[8 * APITCH]);
                af[mt][2] = f2tf(ap[4]);
                af[mt][3] = f2tf(ap[8 * APITCH + 4]);
            }
            uint32_t bf[8][2];
#pragma unroll
            for (int nt = 0; nt < 8; nt++) {
                const float* bp = &Bb[(kb + lc) * BPITCH + wn + nt * 8 + lr];
                bf[nt][0] = f2tf(bp[0]);
                bf[nt][1] = f2tf(bp[4 * BPITCH]);
            }
#pragma unroll
            for (int mt = 0; mt < 2; mt++)
#pragma unroll
                for (int nt = 0; nt < 8; nt++)
                    mma_tf32(c[mt][nt], af[mt][0], af[mt][1], af[mt][2], af[mt][3],
                             bf[nt][0], bf[nt][1]);
        }
        __syncthreads();
    }

#pragma unroll
    for (int nt = 0; nt < 8; nt++) {
        const int col = n0 + wn + nt * 8 + lc * 2;
        const float2 bj = *(const float2*)&bias[col];
#pragma unroll
        for (int mt = 0; mt < 2; mt++) {
            const int row0 = m0 + wm + mt * 16 + lr;
            float2 v0, v1;
            v0.x = c[mt][nt][0] + bj.x;  v0.y = c[mt][nt][1] + bj.y;
            v1.x = c[mt][nt][2] + bj.x;  v1.y = c[mt][nt][3] + bj.y;
            *(float2*)&C[(size_t)row0 * N + col]       = v0;
            *(float2*)&C[(size_t)(row0 + 8) * N + col] = v1;
        }
    }
}

// ----------------------------------------------------------------------------
// Flash attention v4 — tensor-core (tf32 mma) QK^T and PV, online softmax.
// CTA = (b, h, 128 q-rows), 8 warps; warp owns 16 q-rows. KV tile = 64.
// Fragment maps identical to the validated GEMM (m16n8k8, .row.col).
// Pitches: A-operands (Qs, Ps) 68 (=4 mod 32, conflict-free 4*lr+lc);
//          B-operands (Kt, Vs) 72 (=8 mod 32, conflict-free 8*lc+lr).
// Q pre-scaled by 0.125 (exact) and all smem operands rna-rounded to tf32.
// ----------------------------------------------------------------------------
#define QPITCH 68
#define KPITCH 72
#define VPITCH 72
#define PPITCH 68
#define FA_SMEM_FLOATS (128*QPITCH + 64*KPITCH + 64*VPITCH + 128*PPITCH)

extern __shared__ float fa_sm[];

__global__ __launch_bounds__(256, 2)
void flash_attn_mma_kernel(const float* __restrict__ Q, const float* __restrict__ K,
                           const float* __restrict__ V, float* __restrict__ O)
{
    float* Qs = fa_sm;                      // [128][68] Q (scaled, tf32)
    float* Kt = Qs + 128 * QPITCH;          // [64][72]  K^T: Kt[dk][key]
    float* Vs = Kt + 64 * KPITCH;           // [64][72]  V natural: Vs[key][dk]
    float* Ps = Vs + 64 * VPITCH;           // [128][68] probs (tf32)

    const int tid  = threadIdx.x;
    const int wid  = tid >> 5;
    const int lane = tid & 31;
    const int lr   = lane >> 2;   // 0..7
    const int lc   = lane & 3;    // 0..3
    const int wm   = wid * 16;    // warp's q-row base within tile
    const int q0   = blockIdx.x * 128;
    const int h    = blockIdx.y;
    const int b    = blockIdx.z;
    const int hoff = h * DK_;

    // Load Q tile (128x64): scale by 1/sqrt(64) (exact pow2) + tf32 round
#pragma unroll
    for (int i = 0; i < 8; i++) {
        int idx = tid + i * 256;
        int row = idx >> 4;
        int cg  = (idx & 15) * 4;
        float4 v = *(const float4*)&Q[(size_t)(b * S_ + q0 + row) * D_ + hoff + cg];
        float4 r;
        r.x = f2tff(v.x * 0.125f);
        r.y = f2tff(v.y * 0.125f);
        r.z = f2tff(v.z * 0.125f);
        r.w = f2tff(v.w * 0.125f);
        *(float4*)&Qs[row * QPITCH + cg] = r;
    }

    // softmax state for this thread's two rows (wm+lr, wm+lr+8)
    float m0 = -1e30f, m1 = -1e30f, l0 = 0.f, l1 = 0.f;
    float oc[8][4];
#pragma unroll
    for (int nt = 0; nt < 8; nt++)
#pragma unroll
        for (int j = 0; j < 4; j++) oc[nt][j] = 0.f;

    for (int kt = 0; kt < S_; kt += 64) {
        __syncthreads();   // prior tile's PV reads of Kt/Vs complete (iter0: Qs stores)

        // K tile: transpose store -> Kt[dk][key], tf32-rounded.
        // Within a warp: cg fixed, key = consecutive lanes -> bank-conflict-free.
#pragma unroll
        for (int i = 0; i < 4; i++) {
            int u   = tid + i * 256;
            int key = u & 63;
            int cg  = ((u >> 6) & 15) * 4;
            float4 kv = *(const float4*)&K[(size_t)(b * S_ + kt + key) * D_ + hoff + cg];
            Kt[(cg + 0) * KPITCH + key] = f2tff(kv.x);
            Kt[(cg + 1) * KPITCH + key] = f2tff(kv.y);
            Kt[(cg + 2) * KPITCH + key] = f2tff(kv.z);
            Kt[(cg + 3) * KPITCH + key] = f2tff(kv.w);
        }
        // V tile: natural store, tf32-rounded
#pragma unroll
        for (int i = 0; i < 4; i++) {
            int u   = tid + i * 256;
            int row = u >> 4;            // key 0..63
            int cg  = (u & 15) * 4;
            float4 vv = *(const float4*)&V[(size_t)(b * S_ + kt + row) * D_ + hoff + cg];
            float4 r;
            r.x = f2tff(vv.x);
            r.y = f2tff(vv.y);
            r.z = f2tff(vv.z);
            r.w = f2tff(vv.w);
            *(float4*)&Vs[row * VPITCH + cg] = r;
        }
        __syncthreads();

        // ---- S = Q . K^T  (warp: m16 x n64, k=64) ----
        float sc[8][4];
#pragma unroll
        for (int nt = 0; nt < 8; nt++)
#pragma unroll
            for (int j = 0; j < 4; j++) sc[nt][j] = 0.f;

#pragma unroll
        for (int ks = 0; ks < 8; ks++) {
            const int kb = ks * 8;
            const float* ap = &Qs[(wm + lr) * QPITCH + kb + lc];
            uint32_t a0 = __float_as_uint(ap[0]);
            uint32_t a1 = __float_as_uint(ap[8 * QPITCH]);
            uint32_t a2 = __float_as_uint(ap[4]);
            uint32_t a3 = __float_as_uint(ap[8 * QPITCH + 4]);
#pragma unroll
            for (int nt = 0; nt < 8; nt++) {
                const float* bp = &Kt[(kb + lc) * KPITCH + nt * 8 + lr];
                mma_tf32(sc[nt], a0, a1, a2, a3,
                         __float_as_uint(bp[0]), __float_as_uint(bp[4 * KPITCH]));
            }
        }

        // ---- online softmax on fragments (rows lr and lr+8) ----
        float t0 = -1e30f, t1 = -1e30f;
#pragma unroll
        for (int nt = 0; nt < 8; nt++) {
            t0 = fmaxf(t0, fmaxf(sc[nt][0], sc[nt][1]));
            t1 = fmaxf(t1, fmaxf(sc[nt][2], sc[nt][3]));
        }
        t0 = fmaxf(t0, __shfl_xor_sync(0xffffffffu, t0, 1));
        t0 = fmaxf(t0, __shfl_xor_sync(0xffffffffu, t0, 2));
        t1 = fmaxf(t1, __shfl_xor_sync(0xffffffffu, t1, 1));
        t1 = fmaxf(t1, __shfl_xor_sync(0xffffffffu, t1, 2));

        float mn0 = fmaxf(m0, t0);
        float mn1 = fmaxf(m1, t1);
        float al0 = fexp(m0 - mn0);
        float al1 = fexp(m1 - mn1);
        float ps0 = 0.f, ps1 = 0.f;
#pragma unroll
        for (int nt = 0; nt < 8; nt++) {
            float p0 = fexp(sc[nt][0] - mn0);
            float p1 = fexp(sc[nt][1] - mn0);
            float p2 = fexp(sc[nt][2] - mn1);
            float p3 = fexp(sc[nt][3] - mn1);
            ps0 += p0 + p1;
            ps1 += p2 + p3;
            sc[nt][0] = p0; sc[nt][1] = p1; sc[nt][2] = p2; sc[nt][3] = p3;
        }
        ps0 += __shfl_xor_sync(0xffffffffu, ps0, 1);
        ps0 += __shfl_xor_sync(0xffffffffu, ps0, 2);
        ps1 += __shfl_xor_sync(0xffffffffu, ps1, 1);
        ps1 += __shfl_xor_sync(0xffffffffu, ps1, 2);
        l0 = l0 * al0 + ps0;  m0 = mn0;
        l1 = l1 * al1 + ps1;  m1 = mn1;
#pragma unroll
        for (int nt = 0; nt < 8; nt++) {
            oc[nt][0] *= al0;  oc[nt][1] *= al0;
            oc[nt][2] *= al1;  oc[nt][3] *= al1;
        }

        // ---- store P (tf32-rounded); rows are warp-private -> syncwarp only ----
#pragma unroll
        for (int nt = 0; nt < 8; nt++) {
            float2 w0, w1;
            w0.x = f2tff(sc[nt][0]);  w0.y = f2tff(sc[nt][1]);
            w1.x = f2tff(sc[nt][2]);  w1.y = f2tff(sc[nt][3]);
            *(float2*)&Ps[(wm + lr)     * PPITCH + nt * 8 + lc * 2] = w0;
            *(float2*)&Ps[(wm + lr + 8) * PPITCH + nt * 8 + lc * 2] = w1;
        }
        __syncwarp();

        // ---- O += P . V  (warp: m16 x n64(dk), k=64(key)) ----
#pragma unroll
        for (int ks = 0; ks < 8; ks++) {
            const int kb = ks * 8;
            const float* ap = &Ps[(wm + lr) * PPITCH + kb + lc];
            uint32_t a0 = __float_as_uint(ap[0]);
            uint32_t a1 = __float_as_uint(ap[8 * PPITCH]);
            uint32_t a2 = __float_as_uint(ap[4]);
            uint32_t a3 = __float_as_uint(ap[8 * PPITCH + 4]);
#pragma unroll
            for (int nt = 0; nt < 8; nt++) {
                const float* bp = &Vs[(kb + lc) * VPITCH + nt * 8 + lr];
                mma_tf32(oc[nt], a0, a1, a2, a3,
                         __float_as_uint(bp[0]), __float_as_uint(bp[4 * VPITCH]));
            }
        }
    }

    // epilogue: normalize + write [B,S,D]
    float inv0 = 1.f / l0;
    float inv1 = 1.f / l1;
    const size_t r0 = (size_t)(b * S_ + q0 + wm + lr) * D_ + hoff;
    const size_t r1 = (size_t)(b * S_ + q0 + wm + lr + 8) * D_ + hoff;
#pragma unroll
    for (int nt = 0; nt < 8; nt++) {
        const int col = nt * 8 + lc * 2;
        float2 w0, w1;
        w0.x = oc[nt][0] * inv0;  w0.y = oc[nt][1] * inv0;
        w1.x = oc[nt][2] * inv1;  w1.y = oc[nt][3] * inv1;
        *(float2*)&O[r0 + col] = w0;
        *(float2*)&O[r1 + col] = w1;
    }
}

// ----------------------------------------------------------------------------
// Launch: 3 projection GEMMs -> mma flash attention -> output GEMM
// ----------------------------------------------------------------------------
extern "C" void kernel_launch(void* const* d_in, const int* in_sizes, int n_in,
                              void* d_out, int out_size)
{
    const float* query = (const float*)d_in[0];
    const float* value = (const float*)d_in[1];
    const float* key   = (const float*)d_in[2];
    const float* Wq = (const float*)d_in[3];
    const float* bq = (const float*)d_in[4];
    const float* Wk = (const float*)d_in[5];
    const float* bk = (const float*)d_in[6];
    const float* Wv = (const float*)d_in[7];
    const float* bv = (const float*)d_in[8];
    const float* Wo = (const float*)d_in[9];
    const float* bo = (const float*)d_in[10];
    float* out = (float*)d_out;

    float *Qp, *Kp, *Vp, *AOp;
    cudaGetSymbolAddress((void**)&Qp,  g_Q);
    cudaGetSymbolAddress((void**)&Kp,  g_K);
    cudaGetSymbolAddress((void**)&Vp,  g_V);
    cudaGetSymbolAddress((void**)&AOp, g_AO);

    const int gemm_smem = 2 * (ABUF + BBUF) * (int)sizeof(float);  // 70656 B
    cudaFuncSetAttribute(tf32_gemm_bias_kernel,
                         cudaFuncAttributeMaxDynamicSharedMemorySize, gemm_smem);

    dim3 gemm_grid(D_ / 128, M_ / 128);
    tf32_gemm_bias_kernel<<<gemm_grid, 256, gemm_smem>>>(query, Wq, bq, Qp, M_, D_, D_);
    tf32_gemm_bias_kernel<<<gemm_grid, 256, gemm_smem>>>(key,   Wk, bk, Kp, M_, D_, D_);
    tf32_gemm_bias_kernel<<<gemm_grid, 256, gemm_smem>>>(value, Wv, bv, Vp, M_, D_, D_);

    const int fa_smem = FA_SMEM_FLOATS * (int)sizeof(float);   // 106,496 B
    cudaFuncSetAttribute(flash_attn_mma_kernel,
                         cudaFuncAttributeMaxDynamicSharedMemorySize, fa_smem);
    flash_attn_mma_kernel<<<dim3(S_ / 128, H_, B_), 256, fa_smem>>>(Qp, Kp, Vp, AOp);

    tf32_gemm_bias_kernel<<<gemm_grid, 256, gemm_smem>>>(AOp, Wo, bo, out, M_, D_, D_);
}